// round 16
// baseline (speedup 1.0000x reference)
#include <cuda_runtime.h>
#include <cuda_fp16.h>
#include <cstdint>

// Problem constants (from reference)
#define BATCHES 8
#define NP 4096
#define STRIDE 4
#define KNN 32
#define NS (NP / STRIDE)          // 1024 samples per batch
#define NSAMP (BATCHES * NS)      // 8192
#define NPTS (BATCHES * NP)       // 32768
#define DIN 64
#define H1DIM 128
#define H2DIM 256

// Output layout (float32 concat of the reference tuple)
#define XOUT_OFF   0
#define POS_OFF    (NSAMP * H2DIM)                 // 2097152
#define BATCH_OFF  (POS_OFF + NSAMP * 3)           // 2121728
#define IDX_OFF    (BATCH_OFF + NSAMP)             // 2129920
#define TOTAL_OUT  (IDX_OFF + NSAMP)               // 2138112

// Scratch (static __device__ arrays: no allocation)
__device__ float g_xw1[NPTS * H1DIM];     // 16 MB: x @ W1[:64]
__device__ int   g_nbr[NSAMP * KNN];      // 1 MB : local neighbor indices
// W2 packed as per-lane mma.sync B-fragments, fp16:
// flat index = wid*2048 + kt*256 + t*64 + h*32 + lane
__device__ uint32_t g_w2frag[16384];      // 64 KB

__device__ __forceinline__ unsigned long long umin64(unsigned long long a,
                                                     unsigned long long b) {
    return b < a ? b : a;
}
__device__ __forceinline__ unsigned long long umax64(unsigned long long a,
                                                     unsigned long long b) {
    return a < b ? b : a;
}

static __device__ __forceinline__ uint32_t smem_u32(const void* p) {
    uint32_t a;
    asm("{ .reg .u64 t; cvta.to.shared.u64 t, %1; cvt.u32.u64 %0, t; }"
        : "=r"(a) : "l"(p));
    return a;
}

// mma.sync fp16 (sm_80+, valid at .target sm_100)
__device__ __forceinline__ void mma_f16(float* d, const uint32_t* a,
                                        const uint32_t* b) {
    asm volatile(
        "mma.sync.aligned.m16n8k16.row.col.f32.f16.f16.f32 "
        "{%0,%1,%2,%3}, {%4,%5,%6,%7}, {%8,%9}, {%0,%1,%2,%3};"
        : "+f"(d[0]), "+f"(d[1]), "+f"(d[2]), "+f"(d[3])
        : "r"(a[0]), "r"(a[1]), "r"(a[2]), "r"(a[3]), "r"(b[0]), "r"(b[1]));
}
__device__ __forceinline__ void ldm_x4(uint32_t* r, uint32_t addr) {
    asm volatile(
        "ldmatrix.sync.aligned.m8n8.x4.shared.b16 {%0,%1,%2,%3}, [%4];"
        : "=r"(r[0]), "=r"(r[1]), "=r"(r[2]), "=r"(r[3]) : "r"(addr));
}

// ---------------------------------------------------------------------------
// Warp-cooperative bitonic sort of N = R*32 u64 keys (R regs/lane).
// ---------------------------------------------------------------------------
template <int R>
__device__ __forceinline__ void bitonic_sort(unsigned long long k[R], int lane) {
    const int N = R * 32;
#pragma unroll
    for (int kk = 2; kk <= N; kk <<= 1) {
#pragma unroll
        for (int j = kk >> 1; j > 0; j >>= 1) {
            if (j >= 32) {
                const int rj = j >> 5;
#pragma unroll
                for (int r = 0; r < R; ++r) {
                    if ((r & rj) == 0) {
                        const int r2 = r | rj;
                        const bool asc = (((r * 32) & kk) == 0);
                        const unsigned long long lo = umin64(k[r], k[r2]);
                        const unsigned long long hi = umax64(k[r], k[r2]);
                        k[r]  = asc ? lo : hi;
                        k[r2] = asc ? hi : lo;
                    }
                }
            } else {
#pragma unroll
                for (int r = 0; r < R; ++r) {
                    const unsigned long long other =
                        __shfl_xor_sync(0xffffffffu, k[r], j);
                    const int v = r * 32 + lane;
                    const bool asc     = ((v & kk) == 0);
                    const bool upper   = ((lane & j) != 0);
                    const bool keepMin = (asc != upper);
                    const unsigned long long mn = umin64(k[r], other);
                    const unsigned long long mx = umax64(k[r], other);
                    k[r] = keepMin ? mn : mx;
                }
            }
        }
    }
}

// ---------------------------------------------------------------------------
// MERGED prep kernel (R14/R15, proven): blocks [0,512) = KNN, [512,2560) =
// xw1, [2560,2624) = w2frag.
// ---------------------------------------------------------------------------
#define SPB2 16
#define CAP  256
#define KNN_BLOCKS  (BATCHES * (NS / SPB2))          // 512
#define XW1_BLOCKS  (NPTS / 16)                      // 2048
#define W2F_BLOCKS  64
#define PRE_GRID    (KNN_BLOCKS + XW1_BLOCKS + W2F_BLOCKS)
#define PRE_SMEM    (3 * NP * 4 + SPB2 * CAP * 8 + SPB2 * 8 * 8 + SPB2 * 4)

__device__ void knn_body(const float* __restrict__ pos, char* smraw, int blk) {
    float* sm = (float*)smraw;
    float* px = sm;
    float* py = sm + NP;
    float* pz = sm + 2 * NP;
    unsigned long long* lists = (unsigned long long*)(sm + 3 * NP); // [16][CAP]
    unsigned long long* warpT = lists + SPB2 * CAP;                 // [16][8]
    int* s_cnt = (int*)(warpT + SPB2 * 8);                          // [16]

    const int tid  = threadIdx.x;
    const int lane = tid & 31;
    const int wid  = tid >> 5;
    const int b    = blk / (NS / SPB2);
    const int grp  = blk % (NS / SPB2);

    for (int i = tid; i < NP; i += 256) {
        px[i] = pos[(b * NP + i) * 3 + 0];
        py[i] = pos[(b * NP + i) * 3 + 1];
        pz[i] = pos[(b * NP + i) * 3 + 2];
    }
    if (tid < SPB2) s_cnt[tid] = 0;
    __syncthreads();

    for (int si = 0; si < SPB2; ++si) {
        const int s_local = grp * SPB2 + si;
        const int c_local = s_local * STRIDE;
        const float ax = px[c_local], ay = py[c_local], az = pz[c_local];
        const float as2 = __fadd_rn(__fadd_rn(__fmul_rn(ax, ax), __fmul_rn(ay, ay)),
                                    __fmul_rn(az, az));

        unsigned long long keys[16];
#pragma unroll
        for (int t = 0; t < 16; ++t) {
            const int i = tid + t * 256;
            const float bx = px[i], by = py[i], bz = pz[i];
            const float bn2 = __fadd_rn(__fadd_rn(__fmul_rn(bx, bx), __fmul_rn(by, by)),
                                        __fmul_rn(bz, bz));
            const float dot = __fadd_rn(__fadd_rn(__fmul_rn(ax, bx), __fmul_rn(ay, by)),
                                        __fmul_rn(az, bz));
            const float d2  = __fadd_rn(__fadd_rn(as2, bn2), -__fmul_rn(2.0f, dot));
            unsigned u = __float_as_uint(d2);
            unsigned kk = (u & 0x80000000u) ? ~u : (u | 0x80000000u);
            keys[t] = (((unsigned long long)kk) << 32) | (unsigned)i;
        }
        unsigned long long lmin = keys[0];
#pragma unroll
        for (int t = 1; t < 16; ++t) lmin = umin64(lmin, keys[t]);

        unsigned long long tm[1] = { lmin };
        bitonic_sort<1>(tm, lane);
        const unsigned long long Tw = __shfl_sync(0xffffffffu, tm[0], 3);
        if (lane == 0) warpT[si * 8 + wid] = Tw;
        __syncthreads();

        unsigned long long T = warpT[si * 8 + 0];
#pragma unroll
        for (int q = 1; q < 8; ++q) T = umax64(T, warpT[si * 8 + q]);

        int cnt = 0;
#pragma unroll
        for (int t = 0; t < 16; ++t) cnt += (keys[t] <= T) ? 1 : 0;
        int base = atomicAdd(&s_cnt[si], cnt);
        unsigned long long* lst = lists + si * CAP;
#pragma unroll
        for (int t = 0; t < 16; ++t) {
            if (keys[t] <= T) {
                if (base < CAP) lst[base] = keys[t];
                ++base;
            }
        }
    }
    __syncthreads();

    for (int q = 0; q < 2; ++q) {
        const int si = wid + q * 8;
        int C = s_cnt[si];
        if (C > CAP) C = CAP;
        const int s_local = grp * SPB2 + si;
        const int sidx = b * NS + s_local;
        const unsigned long long* lst = lists + si * CAP;

        if (C <= 64) {
            unsigned long long k2[2];
#pragma unroll
            for (int r = 0; r < 2; ++r) {
                const int v = r * 32 + lane;
                k2[r] = (v < C) ? lst[v] : 0xffffffffffffffffull;
            }
            bitonic_sort<2>(k2, lane);
            g_nbr[sidx * KNN + lane] = (int)(unsigned)(k2[0] & 0xffffffffull);
        } else if (C <= 128) {
            unsigned long long k4[4];
#pragma unroll
            for (int r = 0; r < 4; ++r) {
                const int v = r * 32 + lane;
                k4[r] = (v < C) ? lst[v] : 0xffffffffffffffffull;
            }
            bitonic_sort<4>(k4, lane);
            g_nbr[sidx * KNN + lane] = (int)(unsigned)(k4[0] & 0xffffffffull);
        } else {
            unsigned long long k8[8];
#pragma unroll
            for (int r = 0; r < 8; ++r) {
                const int v = r * 32 + lane;
                k8[r] = (v < C) ? lst[v] : 0xffffffffffffffffull;
            }
            bitonic_sort<8>(k8, lane);
            g_nbr[sidx * KNN + lane] = (int)(unsigned)(k8[0] & 0xffffffffull);
        }
    }
}

__device__ void xw1_body(const float* __restrict__ x,
                         const float* __restrict__ W1, char* smraw, int blk) {
    float* xs = (float*)smraw;            // 16 * 64 floats
    const int p0 = blk * 16;
    const int tid = threadIdx.x;
    for (int i = tid; i < 16 * DIN; i += 256) xs[i] = x[p0 * DIN + i];
    __syncthreads();

    const int j = tid & 127;
    const int h = tid >> 7;               // points 8h..8h+7
    float acc[8];
#pragma unroll
    for (int p = 0; p < 8; ++p) acc[p] = 0.f;
#pragma unroll
    for (int f = 0; f < DIN; ++f) {
        float w = W1[f * H1DIM + j];
#pragma unroll
        for (int p = 0; p < 8; ++p)
            acc[p] = fmaf(xs[(h * 8 + p) * DIN + f], w, acc[p]);
    }
#pragma unroll
    for (int p = 0; p < 8; ++p)
        g_xw1[(p0 + h * 8 + p) * H1DIM + j] = acc[p];
}

__device__ void w2frag_body(const float* __restrict__ W2, int blk) {
    const int idx  = blk * 256 + threadIdx.x;   // 0..16383
    const int lane = idx & 31;
    const int h    = (idx >> 5) & 1;
    const int t    = (idx >> 6) & 3;
    const int kt   = (idx >> 8) & 7;
    const int w    = (idx >> 11) & 7;

    const int k = kt * 16 + (lane & 3) * 2 + 8 * h;
    const int n = w * 32 + t * 8 + (lane >> 2);

    const __half p0 = __float2half_rn(W2[k * H2DIM + n]);
    const __half p1 = __float2half_rn(W2[(k + 1) * H2DIM + n]);
    unsigned short u0, u1;
    memcpy(&u0, &p0, 2);
    memcpy(&u1, &p1, 2);
    g_w2frag[idx] = (uint32_t)u0 | ((uint32_t)u1 << 16);
}

__global__ void __launch_bounds__(256) k_pre(const float* __restrict__ x,
                                             const float* __restrict__ pos,
                                             const float* __restrict__ W1,
                                             const float* __restrict__ W2) {
    extern __shared__ char smraw[];
    const int bid = blockIdx.x;
    if (bid < KNN_BLOCKS) {
        knn_body(pos, smraw, bid);
    } else if (bid < KNN_BLOCKS + XW1_BLOCKS) {
        xw1_body(x, W1, smraw, bid - KNN_BLOCKS);
    } else {
        w2frag_body(W2, bid - KNN_BLOCKS - XW1_BLOCKS);
    }
}

// ---------------------------------------------------------------------------
// Kernel 3: MLP + max-pool, persistent CTAs, FUSED pipeline:
// per phase (one barrier): stage meta(g+2G); then per s4 chunk:
//   produce(s4 of g+G -> h1[nxt])  interleaved with  GEMM(s4 of g <- h1[cur]).
// Buffer parity: phase i writes meta[i&1] & h1[(i+1)&1], reads meta[(i+1)&1]
// & h1[i&1]; every write->read crossing passes exactly one barrier.
// ---------------------------------------------------------------------------
#define SPB3 4
#define NGRP (NSAMP / SPB3)                 // 2048
#define ROWSTRIDE 136                       // fp16 elements per h1 row
#define H1_BYTES  (SPB3 * 32 * ROWSTRIDE * 2)  // 34816
#define SM_DYN    (2 * H1_BYTES)            // 69632
#define MLP_GRID  296

__global__ void __launch_bounds__(256, 2) k_mlp(const float* __restrict__ pos,
                                                const float* __restrict__ W1,
                                                const float* __restrict__ b1,
                                                const float* __restrict__ b2,
                                                float* __restrict__ out,
                                                int write_extras) {
    extern __shared__ __align__(16) char dyn[];
    __half* h1b0 = (__half*)dyn;
    __half* h1b1 = (__half*)(dyn + H1_BYTES);

    __shared__ float w1r[3][H1DIM];
    __shared__ float b1s[H1DIM];
    __shared__ float b2s[H2DIM];
    __shared__ float npx[2][128], npy[2][128], npz[2][128];
    __shared__ int   gix[2][128];
    __shared__ float psmp[2][4][3];

    const int tid  = threadIdx.x;
    const int lane = tid & 31;
    const int wid  = tid >> 5;
    const int G    = gridDim.x;

    // ---- B-fragments: 64 u32 per thread, loaded once per block ----
    uint32_t bfr[8][4][2];
    {
        const uint32_t* fb = g_w2frag + wid * 2048 + lane;
#pragma unroll
        for (int u = 0; u < 64; ++u) {
            const int kt = u >> 3, t = (u >> 1) & 3, h = u & 1;
            bfr[kt][t][h] = fb[u * 32];
        }
    }

    if (tid < H1DIM) {
        w1r[0][tid] = W1[64 * H1DIM + tid];
        w1r[1][tid] = W1[65 * H1DIM + tid];
        w1r[2][tid] = W1[66 * H1DIM + tid];
        b1s[tid]    = b1[tid];
    }
    b2s[tid] = b2[tid];

    const int j    = tid & 127;           // hidden channel
    const int half = tid >> 7;            // neighbor parity
    const int lrow = lane & 15;
    const int lcol = (lane >> 4) & 1;

    auto stage_meta = [&](int g, int mb) {
        if (tid < 128) {
            const int si = tid >> 5;
            const int s  = g * 4 + si;
            const int b  = s >> 10;
            const int nl = g_nbr[s * KNN + (tid & 31)];
            const int gg = b * NP + nl;
            gix[mb][tid] = gg;
            npx[mb][tid] = pos[3 * gg];
            npy[mb][tid] = pos[3 * gg + 1];
            npz[mb][tid] = pos[3 * gg + 2];
        }
        if (tid < 16) {
            const int si = tid >> 2, c = tid & 3;
            if (c < 3) {
                const int s = g * 4 + si;
                const int b = s >> 10;
                const int p = b * NP + (s & (NS - 1)) * STRIDE;
                psmp[mb][si][c] = pos[3 * p + c];
            }
        }
    };

    auto produce_chunk = [&](int si, int mb, __half* hb) {
        const float psx = psmp[mb][si][0];
        const float psy = psmp[mb][si][1];
        const float psz = psmp[mb][si][2];
#pragma unroll
        for (int kk = 0; kk < 16; ++kk) {
            const int k  = kk * 2 + half;
            const int gg = gix[mb][si * 32 + k];
            float rx = npx[mb][si * 32 + k] - psx;
            float ry = npy[mb][si * 32 + k] - psy;
            float rz = npz[mb][si * 32 + k] - psz;
            float v = g_xw1[gg * H1DIM + j];
            v = fmaf(rx, w1r[0][j], v);
            v = fmaf(ry, w1r[1][j], v);
            v = fmaf(rz, w1r[2][j], v);
            v += b1s[j];
            v = fmaxf(v, 0.f);
            hb[(si * 32 + k) * ROWSTRIDE + j] = __float2half_rn(v);
        }
    };

    const int g0 = blockIdx.x;            // < G <= NGRP

    // ---- prologue: meta(g0) -> buf0, produce(g0) -> h1b0, meta(g0+G)->buf1
    stage_meta(g0, 0);
    __syncthreads();                      // meta(g0) + consts visible
    if (g0 + G < NGRP) stage_meta(g0 + G, 1);
#pragma unroll
    for (int si = 0; si < 4; ++si) produce_chunk(si, 0, h1b0);
    __syncthreads();                      // h1(g0) ready

    int i = 0;
    for (int g = g0; g < NGRP; g += G, ++i) {
        const int cur = i & 1;
        const int nxt = cur ^ 1;
        __half* h1cur = cur ? h1b1 : h1b0;
        __half* h1nxt = cur ? h1b0 : h1b1;
        const int gn  = g + G;
        const int gnn = g + 2 * G;

        if (gnn < NGRP) stage_meta(gnn, cur);   // overlaps everything below
        const uint32_t h1_u = smem_u32(h1cur);

        for (int s4 = 0; s4 < 4; ++s4) {
            // produce chunk of next group (xw1 LDGs overlap this GEMM)
            if (gn < NGRP) produce_chunk(s4, nxt, h1nxt);

            float acc[2][4][4];
#pragma unroll
            for (int mt = 0; mt < 2; ++mt)
#pragma unroll
                for (int nt = 0; nt < 4; ++nt)
#pragma unroll
                    for (int e = 0; e < 4; ++e) acc[mt][nt][e] = 0.f;

#pragma unroll
            for (int kt = 0; kt < 8; ++kt) {
                uint32_t afr[2][4];
#pragma unroll
                for (int mt = 0; mt < 2; ++mt) {
                    const uint32_t byteoff =
                        (uint32_t)(((s4 * 32 + mt * 16 + lrow) * ROWSTRIDE +
                                    kt * 16 + lcol * 8) * 2);
                    ldm_x4(afr[mt], h1_u + byteoff);
                }
#pragma unroll
                for (int mt = 0; mt < 2; ++mt)
#pragma unroll
                    for (int nt = 0; nt < 4; ++nt)
                        mma_f16(acc[mt][nt], afr[mt], bfr[kt][nt]);
            }

            const int s = g * 4 + s4;
#pragma unroll
            for (int nt = 0; nt < 4; ++nt)
#pragma unroll
                for (int par = 0; par < 2; ++par) {
                    float m = fmaxf(fmaxf(acc[0][nt][par], acc[0][nt][par + 2]),
                                    fmaxf(acc[1][nt][par], acc[1][nt][par + 2]));
                    m = fmaxf(m, __shfl_xor_sync(0xffffffffu, m, 4));
                    m = fmaxf(m, __shfl_xor_sync(0xffffffffu, m, 8));
                    m = fmaxf(m, __shfl_xor_sync(0xffffffffu, m, 16));
                    if (lane < 4) {
                        const int c = wid * 32 + nt * 8 + (lane & 3) * 2 + par;
                        out[XOUT_OFF + s * H2DIM + c] = fmaxf(m + b2s[c], 0.f);
                    }
                }
        }

        if (write_extras) {
#pragma unroll
            for (int si = 0; si < 4; ++si) {
                const int s = g * 4 + si;
                const int b = s >> 10;
                const int p = b * NP + (s & (NS - 1)) * STRIDE;
                if (tid < 3)  out[POS_OFF + s * 3 + tid] = pos[3 * p + tid];
                if (tid == 3) out[BATCH_OFF + s] = (float)b;
                if (tid == 4) out[IDX_OFF + s]   = (float)p;
            }
        }
        __syncthreads();   // single barrier per group: swaps buffer roles
    }
}

// ---------------------------------------------------------------------------
extern "C" void kernel_launch(void* const* d_in, const int* in_sizes, int n_in,
                              void* d_out, int out_size) {
    const float* x   = (const float*)d_in[0];
    const float* pos = (const float*)d_in[1];
    const float* W1  = (const float*)d_in[3];
    const float* b1  = (const float*)d_in[4];
    const float* W2  = (const float*)d_in[5];
    const float* b2  = (const float*)d_in[6];
    float* out = (float*)d_out;

    const int write_extras = (out_size >= TOTAL_OUT) ? 1 : 0;

    cudaFuncSetAttribute(k_pre, cudaFuncAttributeMaxDynamicSharedMemorySize,
                         PRE_SMEM);
    k_pre<<<PRE_GRID, 256, PRE_SMEM>>>(x, pos, W1, W2);

    cudaFuncSetAttribute(k_mlp, cudaFuncAttributeMaxDynamicSharedMemorySize,
                         SM_DYN);
    k_mlp<<<MLP_GRID, 256, SM_DYN>>>(pos, W1, b1, b2, out, write_extras);
}